// round 12
// baseline (speedup 1.0000x reference)
#include <cuda_runtime.h>
#include <cuda_fp16.h>
#include <math.h>
#include <stdint.h>

#define L_SEQ 1024
#define H_DIM 2048
#define DI    4096
#define DT_R  128
#define NS    16
#define KC    4
#define FF    8192
#define KSPL  8

// ---------------- scratch ----------------
__device__ float g_proj [L_SEQ * 2 * DI];
__device__ float g_h    [L_SEQ * DI];
__device__ float g_part [KSPL * L_SEQ * 160];
__device__ float g_kp   [2 * L_SEQ * H_DIM];    // split-K partials for out/down GEMMs
__device__ float g_Bn   [L_SEQ * NS];
__device__ float g_Cn   [L_SEQ * NS];
__device__ float g_delta[L_SEQ * DI];
__device__ float g_res2 [L_SEQ * H_DIM];
// fp16 activations
__device__ __half g_xnh  [L_SEQ * H_DIM];
__device__ __half g_hh   [L_SEQ * DI];
__device__ __half g_dtnh [L_SEQ * DT_R];
__device__ __half g_yh   [L_SEQ * DI];
__device__ __half g_xn2h [L_SEQ * H_DIM];
__device__ __half g_acth [L_SEQ * FF];
// fp16 weights
__device__ __half g_w_in [2 * DI * H_DIM];
__device__ __half g_w_x  [160 * DI];
__device__ __half g_w_dt [DI * DT_R];
__device__ __half g_w_out[H_DIM * DI];
__device__ __half g_w_gu [2 * FF * H_DIM];
__device__ __half g_w_dn [H_DIM * FF];

// ================= PTX helpers =================
__device__ __forceinline__ uint32_t smem_u32(const void* p) {
    uint32_t a;
    asm("{ .reg .u64 t; cvta.to.shared.u64 t, %1; cvt.u32.u64 %0, t; }" : "=r"(a) : "l"(p));
    return a;
}
__device__ __forceinline__ void ldsm4(uint32_t& r0, uint32_t& r1, uint32_t& r2, uint32_t& r3, uint32_t a) {
    asm volatile("ldmatrix.sync.aligned.m8n8.x4.shared.b16 {%0,%1,%2,%3}, [%4];"
                 : "=r"(r0), "=r"(r1), "=r"(r2), "=r"(r3) : "r"(a));
}
__device__ __forceinline__ void mma16816(float* c, const uint32_t* a, const uint32_t* b) {
    asm volatile("mma.sync.aligned.m16n8k16.row.col.f32.f16.f16.f32 "
                 "{%0,%1,%2,%3}, {%4,%5,%6,%7}, {%8,%9}, {%0,%1,%2,%3};"
                 : "+f"(c[0]), "+f"(c[1]), "+f"(c[2]), "+f"(c[3])
                 : "r"(a[0]), "r"(a[1]), "r"(a[2]), "r"(a[3]), "r"(b[0]), "r"(b[1]));
}

__device__ __forceinline__ float silu_f(float x) { return x / (1.f + __expf(-x)); }

// ================= fp32 -> fp16 convert (4 float4 per thread) =================
__global__ void __launch_bounds__(256) f2h_kernel(const float4* __restrict__ s,
                                                  uint2* __restrict__ d, int n4) {
    int base = (blockIdx.x * 256 + threadIdx.x) * 4;
    if (base + 3 >= n4) {
        for (int j = 0; j < 4; j++) {
            int i = base + j;
            if (i < n4) {
                float4 v = s[i];
                __half2 a = __floats2half2_rn(v.x, v.y);
                __half2 b = __floats2half2_rn(v.z, v.w);
                uint2 o;
                o.x = *reinterpret_cast<uint32_t*>(&a);
                o.y = *reinterpret_cast<uint32_t*>(&b);
                d[i] = o;
            }
        }
        return;
    }
    float4 v0 = s[base + 0];
    float4 v1 = s[base + 1];
    float4 v2 = s[base + 2];
    float4 v3 = s[base + 3];
    #pragma unroll
    for (int j = 0; j < 4; j++) {
        float4 v = (j == 0) ? v0 : (j == 1) ? v1 : (j == 2) ? v2 : v3;
        __half2 a = __floats2half2_rn(v.x, v.y);
        __half2 b = __floats2half2_rn(v.z, v.w);
        uint2 o;
        o.x = *reinterpret_cast<uint32_t*>(&a);
        o.y = *reinterpret_cast<uint32_t*>(&b);
        d[base + j] = o;
    }
}

// ================= split-K reduce + residual: dst = res + p0 + p1 =================
__global__ void __launch_bounds__(256) kred_kernel(
    const float4* __restrict__ p, const float4* __restrict__ res,
    float4* __restrict__ dst, int n4)
{
    int i = blockIdx.x * 256 + threadIdx.x;
    if (i >= n4) return;
    float4 a = p[i];
    float4 b = p[i + n4];
    float4 r = res[i];
    dst[i] = make_float4(r.x + a.x + b.x, r.y + a.y + b.y,
                         r.z + a.z + b.z, r.w + a.w + b.w);
}

// ================= rmsnorm (fp32 in, fp16 out) =================
__global__ void __launch_bounds__(256) rmsnorm_kernel(
    const float* __restrict__ x, const float* __restrict__ w,
    __half* __restrict__ out, int D)
{
    int row = blockIdx.x;
    const float* xr = x + (size_t)row * D;
    float s = 0.f;
    for (int i = threadIdx.x; i < D; i += 256) { float v = xr[i]; s += v * v; }
    __shared__ float red[8];
    #pragma unroll
    for (int o = 16; o >= 1; o >>= 1) s += __shfl_xor_sync(0xffffffffu, s, o);
    int warp = threadIdx.x >> 5;
    if ((threadIdx.x & 31) == 0) red[warp] = s;
    __syncthreads();
    if (warp == 0) {
        float t = ((threadIdx.x & 31) < 8) ? red[threadIdx.x & 31] : 0.f;
        #pragma unroll
        for (int o = 4; o >= 1; o >>= 1) t += __shfl_xor_sync(0xffffffffu, t, o);
        if (threadIdx.x == 0) red[0] = t;
    }
    __syncthreads();
    float r = rsqrtf(red[0] / (float)D + 1e-6f);
    __half* orow = out + (size_t)row * D;
    for (int i = threadIdx.x; i < D; i += 256)
        orow[i] = __float2half(xr[i] * r * w[i]);
}

// ================= HMMA GEMM: C[M,N] = A[M,K] @ B[N,K]^T (both fp16) =================
// 128x128x32 tile, 8 warps (2x4), warp tile 64x32, m16n8k16.
// Depth-3 pipeline: 2-stage static smem + register staging (LDG t+2 / STS t+1 /
// compute t), ONE __syncthreads per k-tile. 2 CTAs/SM. Split-K via gridDim.z.
// EPI 0: plain fp32   EPI 1: +bias[n] softplus   EPI 2: +extra[m*N+n]
// EPI 3 (IL=true): interleaved gate/up B rows, stores fp16 silu(g)*u to Ch[m*(N/2)+n/2]
template <int EPI, bool IL>
__global__ void __launch_bounds__(256, 2) hgemm(
    const __half* __restrict__ A, const __half* __restrict__ B,
    float* __restrict__ C, int M, int N, int K,
    const float* __restrict__ extra, __half* __restrict__ Ch)
{
    __shared__ __align__(16) __half As[2][128][40];
    __shared__ __align__(16) __half Bs[2][128][40];

    const int tid = threadIdx.x;
    const int lane = tid & 31;
    const int wid = tid >> 5;
    const int wm = wid >> 2;
    const int wn = wid & 3;
    const int bm = blockIdx.y * 128;
    const int bn = blockIdx.x * 128;
    const int Ksub = K / gridDim.z;
    const int kbase = blockIdx.z * Ksub;
    if (gridDim.z > 1) C += (size_t)blockIdx.z * M * N;

    const uint32_t sA = smem_u32(As);
    const uint32_t sB = smem_u32(Bs);
    const uint32_t ABUF = 128 * 40 * 2;

    float c[4][4][4];
    #pragma unroll
    for (int i = 0; i < 4; i++)
        #pragma unroll
        for (int j = 0; j < 4; j++)
            #pragma unroll
            for (int k = 0; k < 4; k++) c[i][j][k] = 0.f;

    const int Fh = N >> 1;
    // loader mapping: tile is 128 rows x 32 halves = 512 uint4; 2 per thread
    const int lrow = tid >> 2;          // 0..63 (+64 on second chunk)
    const int lcq  = (tid & 3) * 8;     // half offset within row

    uint4 ra[2], rb[2];

    auto ldg = [&](int t) {
        int k0 = kbase + t * 32;
        #pragma unroll
        for (int i = 0; i < 2; i++) {
            int row = lrow + i * 64;
            ra[i] = *(const uint4*)(A + (size_t)(bm + row) * K + k0 + lcq);
        }
        #pragma unroll
        for (int i = 0; i < 2; i++) {
            int row = lrow + i * 64;
            int gr = bn + row;
            int wr = IL ? ((gr & 1) ? Fh + (gr >> 1) : (gr >> 1)) : gr;
            rb[i] = (gr < N) ? *(const uint4*)(B + (size_t)wr * K + k0 + lcq)
                             : make_uint4(0u, 0u, 0u, 0u);
        }
    };
    auto sts = [&](int buf) {
        #pragma unroll
        for (int i = 0; i < 2; i++) {
            int row = lrow + i * 64;
            *(uint4*)(&As[buf][row][lcq]) = ra[i];
            *(uint4*)(&Bs[buf][row][lcq]) = rb[i];
        }
    };

    const int nt = Ksub >> 5;
    ldg(0);
    sts(0);
    if (nt > 1) ldg(1);

    for (int t = 0; t < nt; t++) {
        __syncthreads();                 // publishes sts(t); orders compute(t-1) before buf reuse
        if (t + 1 < nt) sts((t + 1) & 1);
        if (t + 2 < nt) ldg(t + 2);

        const uint32_t aBase = sA + (t & 1) * ABUF;
        const uint32_t bBase = sB + (t & 1) * ABUF;
        #pragma unroll
        for (int ks = 0; ks < 2; ks++) {
            uint32_t a[4][4];
            #pragma unroll
            for (int mf = 0; mf < 4; mf++) {
                int row = wm * 64 + mf * 16 + (lane & 15);
                int col = ks * 16 + (lane >> 4) * 8;
                ldsm4(a[mf][0], a[mf][1], a[mf][2], a[mf][3],
                      aBase + (row * 40 + col) * 2);
            }
            uint32_t b[4][2];
            #pragma unroll
            for (int p = 0; p < 2; p++) {
                int row = wn * 32 + p * 16 + (lane & 7) + ((lane >> 4) << 3);
                int col = ks * 16 + ((lane >> 3) & 1) * 8;
                ldsm4(b[2 * p][0], b[2 * p][1], b[2 * p + 1][0], b[2 * p + 1][1],
                      bBase + (row * 40 + col) * 2);
            }
            #pragma unroll
            for (int mf = 0; mf < 4; mf++)
                #pragma unroll
                for (int nf = 0; nf < 4; nf++)
                    mma16816(c[mf][nf], a[mf], b[nf]);
        }
    }

    // epilogue
    #pragma unroll
    for (int mf = 0; mf < 4; mf++) {
        #pragma unroll
        for (int nf = 0; nf < 4; nf++) {
            int m0 = bm + wm * 64 + mf * 16 + (lane >> 2);
            int n0 = bn + wn * 32 + nf * 8 + (lane & 3) * 2;
            if (n0 < N) {
                #pragma unroll
                for (int hh = 0; hh < 2; hh++) {
                    int m = m0 + hh * 8;
                    float v0 = c[mf][nf][hh * 2 + 0];
                    float v1 = c[mf][nf][hh * 2 + 1];
                    if (EPI == 3) {
                        Ch[(size_t)m * Fh + (n0 >> 1)] = __float2half(silu_f(v0) * v1);
                    } else {
                        if (EPI == 1) {
                            v0 += extra[n0];
                            v1 += extra[n0 + 1];
                            v0 = fmaxf(v0, 0.f) + log1pf(__expf(-fabsf(v0)));
                            v1 = fmaxf(v1, 0.f) + log1pf(__expf(-fabsf(v1)));
                        } else if (EPI == 2) {
                            v0 += extra[(size_t)m * N + n0];
                            v1 += extra[(size_t)m * N + n0 + 1];
                        }
                        *(float2*)(C + (size_t)m * N + n0) = make_float2(v0, v1);
                    }
                }
            }
        }
    }
}

// ================= causal depthwise conv + bias + silu =================
__global__ void __launch_bounds__(256) conv_silu_kernel(
    const float* __restrict__ proj, const float* __restrict__ cw,
    const float* __restrict__ cb, float* __restrict__ h, __half* __restrict__ hh)
{
    int idx = blockIdx.x * 256 + threadIdx.x;
    if (idx >= L_SEQ * DI) return;
    int d = idx & (DI - 1);
    int l = idx >> 12;
    float s = cb[d];
    #pragma unroll
    for (int k = 0; k < KC; k++) {
        int ll = l - (KC - 1) + k;
        if (ll >= 0) s = fmaf(proj[(size_t)ll * (2 * DI) + d], cw[d * KC + k], s);
    }
    float v = silu_f(s);
    h[idx] = v;
    hh[idx] = __float2half(v);
}

// ================= segment rmsnorm + split-K reduce =================
__global__ void __launch_bounds__(32) segnorm_kernel(
    const float* __restrict__ part,
    const float* __restrict__ wdt, const float* __restrict__ wb, const float* __restrict__ wc,
    __half* __restrict__ dtnh, float* __restrict__ Bn, float* __restrict__ Cn)
{
    int l = blockIdx.x;
    int lane = threadIdx.x;
    const float* row = part + (size_t)l * 160;
    const size_t SL = (size_t)L_SEQ * 160;

    float v[4];
    float s = 0.f;
    #pragma unroll
    for (int i = 0; i < 4; i++) {
        float acc = 0.f;
        #pragma unroll
        for (int ks = 0; ks < KSPL; ks++) acc += row[ks * SL + lane * 4 + i];
        v[i] = acc;
        s += acc * acc;
    }
    #pragma unroll
    for (int o = 16; o >= 1; o >>= 1) s += __shfl_xor_sync(0xffffffffu, s, o);
    float r = rsqrtf(s / 128.f + 1e-6f);
    #pragma unroll
    for (int i = 0; i < 4; i++)
        dtnh[(size_t)l * 128 + lane * 4 + i] = __float2half(v[i] * r * wdt[lane * 4 + i]);

    float b = 0.f, c = 0.f;
    if (lane < 16) {
        #pragma unroll
        for (int ks = 0; ks < KSPL; ks++) {
            b += row[ks * SL + 128 + lane];
            c += row[ks * SL + 144 + lane];
        }
    }
    float sb = b * b;
    #pragma unroll
    for (int o = 16; o >= 1; o >>= 1) sb += __shfl_xor_sync(0xffffffffu, sb, o);
    float rb = rsqrtf(sb / 16.f + 1e-6f);
    if (lane < 16) Bn[(size_t)l * 16 + lane] = b * rb * wb[lane];

    float sc = c * c;
    #pragma unroll
    for (int o = 16; o >= 1; o >>= 1) sc += __shfl_xor_sync(0xffffffffu, sc, o);
    float rc = rsqrtf(sc / 16.f + 1e-6f);
    if (lane < 16) Cn[(size_t)l * 16 + lane] = c * rc * wc[lane];
}

// ================= selective scan =================
__global__ void __launch_bounds__(256) scan_kernel(
    const float* __restrict__ delta, const float* __restrict__ Bn,
    const float* __restrict__ Cn, const float* __restrict__ h,
    const float* __restrict__ proj, const float* __restrict__ Am,
    const float* __restrict__ Dv, __half* __restrict__ yh)
{
    int tid = blockIdx.x * 256 + threadIdx.x;
    int d = tid >> 4;
    int n = tid & 15;
    float a = Am[d * NS + n];
    float dval = Dv[d];
    float s = 0.f;
    for (int l = 0; l < L_SEQ; l++) {
        float dl = delta[(size_t)l * DI + d];
        float hl = h[(size_t)l * DI + d];
        float bl = Bn[(size_t)l * NS + n];
        float cl = Cn[(size_t)l * NS + n];
        float dA = __expf(dl * a);
        s = fmaf(dA, s, dl * bl * hl);
        float contrib = s * cl;
        contrib += __shfl_xor_sync(0xffffffffu, contrib, 1);
        contrib += __shfl_xor_sync(0xffffffffu, contrib, 2);
        contrib += __shfl_xor_sync(0xffffffffu, contrib, 4);
        contrib += __shfl_xor_sync(0xffffffffu, contrib, 8);
        if (n == 0) {
            float g = proj[(size_t)l * (2 * DI) + DI + d];
            yh[(size_t)l * DI + d] = __float2half((contrib + hl * dval) * silu_f(g));
        }
    }
}

// ================= launch =================
extern "C" void kernel_launch(void* const* d_in, const int* in_sizes, int n_in,
                              void* d_out, int out_size)
{
    const float* hidden      = (const float*)d_in[0];
    const float* in_ln_w     = (const float*)d_in[1];
    const float* pre_ff_ln_w = (const float*)d_in[2];
    const float* in_proj_w   = (const float*)d_in[3];
    const float* conv_w      = (const float*)d_in[4];
    const float* conv_b      = (const float*)d_in[5];
    const float* x_proj_w    = (const float*)d_in[6];
    const float* dt_ln_w     = (const float*)d_in[7];
    const float* b_ln_w      = (const float*)d_in[8];
    const float* c_ln_w      = (const float*)d_in[9];
    const float* dt_proj_w   = (const float*)d_in[10];
    const float* dt_proj_b   = (const float*)d_in[11];
    const float* A           = (const float*)d_in[12];
    const float* Dv          = (const float*)d_in[13];
    const float* out_proj_w  = (const float*)d_in[14];
    const float* gate_up_w   = (const float*)d_in[15];
    const float* down_w      = (const float*)d_in[16];
    float* out = (float*)d_out;

    float *proj, *h, *part, *kp, *Bn, *Cn, *delta, *res2;
    __half *xnh, *hh, *dtnh, *yh, *xn2h, *acth;
    __half *w_in, *w_x, *w_dt, *w_out, *w_gu, *w_dn;
    cudaGetSymbolAddress((void**)&proj,  g_proj);
    cudaGetSymbolAddress((void**)&h,     g_h);
    cudaGetSymbolAddress((void**)&part,  g_part);
    cudaGetSymbolAddress((void**)&kp,    g_kp);
    cudaGetSymbolAddress((void**)&Bn,    g_Bn);
    cudaGetSymbolAddress((void**)&Cn,    g_Cn);
    cudaGetSymbolAddress((void**)&delta, g_delta);
    cudaGetSymbolAddress((void**)&res2,  g_res2);
    cudaGetSymbolAddress((void**)&xnh,   g_xnh);
    cudaGetSymbolAddress((void**)&hh,    g_hh);
    cudaGetSymbolAddress((void**)&dtnh,  g_dtnh);
    cudaGetSymbolAddress((void**)&yh,    g_yh);
    cudaGetSymbolAddress((void**)&xn2h,  g_xn2h);
    cudaGetSymbolAddress((void**)&acth,  g_acth);
    cudaGetSymbolAddress((void**)&w_in,  g_w_in);
    cudaGetSymbolAddress((void**)&w_x,   g_w_x);
    cudaGetSymbolAddress((void**)&w_dt,  g_w_dt);
    cudaGetSymbolAddress((void**)&w_out, g_w_out);
    cudaGetSymbolAddress((void**)&w_gu,  g_w_gu);
    cudaGetSymbolAddress((void**)&w_dn,  g_w_dn);

    // side stream + events for overlapping weight converts (created once;
    // host-side infra only — identical launched work every call)
    static cudaStream_t s2 = nullptr;
    static cudaEvent_t ev_fork = nullptr, ev_join = nullptr;
    if (s2 == nullptr) {
        cudaStreamCreateWithFlags(&s2, cudaStreamNonBlocking);
        cudaEventCreateWithFlags(&ev_fork, cudaEventDisableTiming);
        cudaEventCreateWithFlags(&ev_join, cudaEventDisableTiming);
    }

    auto cvt = [](cudaStream_t st, const float* s, __half* d, int n) {
        int n4 = n / 4;
        int nthreads = (n4 + 3) / 4;
        f2h_kernel<<<(nthreads + 255) / 256, 256, 0, st>>>(
            (const float4*)s, (uint2*)d, n4);
    };

    const int MH4 = (L_SEQ * H_DIM) / 4;   // float4 count for [1024, 2048]

    // fork: side-stream converts for weights consumed later
    cudaEventRecord(ev_fork, 0);
    cudaStreamWaitEvent(s2, ev_fork, 0);
    cvt(s2, x_proj_w,   w_x,   160 * DI);
    cvt(s2, dt_proj_w,  w_dt,  DI * DT_R);
    cvt(s2, out_proj_w, w_out, H_DIM * DI);
    cvt(s2, gate_up_w,  w_gu,  2 * FF * H_DIM);
    cvt(s2, down_w,     w_dn,  H_DIM * FF);
    cudaEventRecord(ev_join, s2);

    // critical path: only w_in is needed immediately
    cvt(0, in_proj_w, w_in, 2 * DI * H_DIM);

    // 1. xn = rmsnorm(hidden) -> fp16
    rmsnorm_kernel<<<L_SEQ, 256>>>(hidden, in_ln_w, xnh, H_DIM);

    // 2. proj = xn @ in_proj_w^T   [1024, 8192], K=2048  (overlaps with S2 converts)
    hgemm<0, false><<<dim3((2 * DI) / 128, L_SEQ / 128, 1), 256>>>(
        xnh, w_in, proj, L_SEQ, 2 * DI, H_DIM, nullptr, nullptr);

    // 3. h = silu(conv(proj[:, :Di]) + b)
    conv_silu_kernel<<<(L_SEQ * DI) / 256, 256>>>(proj, conv_w, conv_b, h, hh);

    // join: all remaining weights must be converted before their consumers
    cudaStreamWaitEvent(0, ev_join, 0);

    // 4. ssm partials = h @ x_proj_w^T   [1024, 160], K=4096, split-K x8
    hgemm<0, false><<<dim3(2, L_SEQ / 128, KSPL), 256>>>(
        hh, w_x, part, L_SEQ, 160, DI, nullptr, nullptr);

    // 5. segment rmsnorms (+ split-K reduce)
    segnorm_kernel<<<L_SEQ, 32>>>(part, dt_ln_w, b_ln_w, c_ln_w, dtnh, Bn, Cn);

    // 6. delta = softplus(dtn @ dt_proj_w^T + b)   [1024, 4096], K=128
    hgemm<1, false><<<dim3(DI / 128, L_SEQ / 128, 1), 256>>>(
        dtnh, w_dt, delta, L_SEQ, DI, DT_R, dt_proj_b, nullptr);

    // 7. selective scan + skip + gate
    scan_kernel<<<(DI * NS) / 256, 256>>>(delta, Bn, Cn, h, proj, A, Dv, yh);

    // 8. out_proj split-K x2 -> partials; res2 = hidden + kp0 + kp1
    hgemm<0, false><<<dim3(H_DIM / 128, L_SEQ / 128, 2), 256>>>(
        yh, w_out, kp, L_SEQ, H_DIM, DI, nullptr, nullptr);
    kred_kernel<<<(MH4 + 255) / 256, 256>>>(
        (const float4*)kp, (const float4*)hidden, (float4*)res2, MH4);

    // 9. xn2 = rmsnorm(res2) -> fp16
    rmsnorm_kernel<<<L_SEQ, 256>>>(res2, pre_ff_ln_w, xn2h, H_DIM);

    // 10+11. act = silu(gate)*up fused into gate_up GEMM (interleaved columns)
    hgemm<3, true><<<dim3((2 * FF) / 128, L_SEQ / 128, 1), 256>>>(
        xn2h, w_gu, nullptr, L_SEQ, 2 * FF, H_DIM, nullptr, acth);

    // 12. down split-K x2 -> partials; out = res2 + kp0 + kp1
    hgemm<0, false><<<dim3(H_DIM / 128, L_SEQ / 128, 2), 256>>>(
        acth, w_dn, kp, L_SEQ, H_DIM, FF, nullptr, nullptr);
    kred_kernel<<<(MH4 + 255) / 256, 256>>>(
        (const float4*)kp, (const float4*)res2, (float4*)out, MH4);
}

// round 13
// speedup vs baseline: 1.0165x; 1.0165x over previous
#include <cuda_runtime.h>
#include <cuda_fp16.h>
#include <math.h>
#include <stdint.h>

#define L_SEQ 1024
#define H_DIM 2048
#define DI    4096
#define DT_R  128
#define NS    16
#define KC    4
#define FF    8192
#define KSPL  8

// ---------------- scratch ----------------
__device__ float g_proj [L_SEQ * 2 * DI];
__device__ float g_h    [L_SEQ * DI];
__device__ float g_part [KSPL * L_SEQ * 160];
__device__ float g_kp   [2 * L_SEQ * H_DIM];    // split-K partials for out/down GEMMs
__device__ float g_Bn   [L_SEQ * NS];
__device__ float g_Cn   [L_SEQ * NS];
__device__ float g_delta[L_SEQ * DI];
__device__ float g_res2 [L_SEQ * H_DIM];
// fp16 activations
__device__ __half g_xnh  [L_SEQ * H_DIM];
__device__ __half g_hh   [L_SEQ * DI];
__device__ __half g_dtnh [L_SEQ * DT_R];
__device__ __half g_yh   [L_SEQ * DI];
__device__ __half g_xn2h [L_SEQ * H_DIM];
__device__ __half g_acth [L_SEQ * FF];
// fp16 weights
__device__ __half g_w_in [2 * DI * H_DIM];
__device__ __half g_w_x  [160 * DI];
__device__ __half g_w_dt [DI * DT_R];
__device__ __half g_w_out[H_DIM * DI];
__device__ __half g_w_gu [2 * FF * H_DIM];
__device__ __half g_w_dn [H_DIM * FF];

// ================= PTX helpers =================
__device__ __forceinline__ uint32_t smem_u32(const void* p) {
    uint32_t a;
    asm("{ .reg .u64 t; cvta.to.shared.u64 t, %1; cvt.u32.u64 %0, t; }" : "=r"(a) : "l"(p));
    return a;
}
__device__ __forceinline__ void cp16(uint32_t dst, const void* src, int sz) {
    asm volatile("cp.async.cg.shared.global [%0], [%1], 16, %2;"
                 :: "r"(dst), "l"(src), "r"(sz));
}
__device__ __forceinline__ void cp_commit() {
    asm volatile("cp.async.commit_group;" ::: "memory");
}
__device__ __forceinline__ void cp_wait0() {
    asm volatile("cp.async.wait_group 0;" ::: "memory");
}
__device__ __forceinline__ void ldsm4(uint32_t& r0, uint32_t& r1, uint32_t& r2, uint32_t& r3, uint32_t a) {
    asm volatile("ldmatrix.sync.aligned.m8n8.x4.shared.b16 {%0,%1,%2,%3}, [%4];"
                 : "=r"(r0), "=r"(r1), "=r"(r2), "=r"(r3) : "r"(a));
}
__device__ __forceinline__ void mma16816(float* c, const uint32_t* a, const uint32_t* b) {
    asm volatile("mma.sync.aligned.m16n8k16.row.col.f32.f16.f16.f32 "
                 "{%0,%1,%2,%3}, {%4,%5,%6,%7}, {%8,%9}, {%0,%1,%2,%3};"
                 : "+f"(c[0]), "+f"(c[1]), "+f"(c[2]), "+f"(c[3])
                 : "r"(a[0]), "r"(a[1]), "r"(a[2]), "r"(a[3]), "r"(b[0]), "r"(b[1]));
}

__device__ __forceinline__ float silu_f(float x) { return x / (1.f + __expf(-x)); }

// ================= fp32 -> fp16 convert (4 float4 per thread) =================
__global__ void __launch_bounds__(256) f2h_kernel(const float4* __restrict__ s,
                                                  uint2* __restrict__ d, int n4) {
    int base = (blockIdx.x * 256 + threadIdx.x) * 4;
    if (base + 3 >= n4) {
        for (int j = 0; j < 4; j++) {
            int i = base + j;
            if (i < n4) {
                float4 v = s[i];
                __half2 a = __floats2half2_rn(v.x, v.y);
                __half2 b = __floats2half2_rn(v.z, v.w);
                uint2 o;
                o.x = *reinterpret_cast<uint32_t*>(&a);
                o.y = *reinterpret_cast<uint32_t*>(&b);
                d[i] = o;
            }
        }
        return;
    }
    float4 v0 = s[base + 0];
    float4 v1 = s[base + 1];
    float4 v2 = s[base + 2];
    float4 v3 = s[base + 3];
    #pragma unroll
    for (int j = 0; j < 4; j++) {
        float4 v = (j == 0) ? v0 : (j == 1) ? v1 : (j == 2) ? v2 : v3;
        __half2 a = __floats2half2_rn(v.x, v.y);
        __half2 b = __floats2half2_rn(v.z, v.w);
        uint2 o;
        o.x = *reinterpret_cast<uint32_t*>(&a);
        o.y = *reinterpret_cast<uint32_t*>(&b);
        d[base + j] = o;
    }
}

// ================= split-K reduce + residual: dst = res + p0 + p1 =================
__global__ void __launch_bounds__(256) kred_kernel(
    const float4* __restrict__ p, const float4* __restrict__ res,
    float4* __restrict__ dst, int n4)
{
    int i = blockIdx.x * 256 + threadIdx.x;
    if (i >= n4) return;
    float4 a = p[i];
    float4 b = p[i + n4];
    float4 r = res[i];
    dst[i] = make_float4(r.x + a.x + b.x, r.y + a.y + b.y,
                         r.z + a.z + b.z, r.w + a.w + b.w);
}

// ================= rmsnorm (fp32 in, fp16 out) =================
__global__ void __launch_bounds__(256) rmsnorm_kernel(
    const float* __restrict__ x, const float* __restrict__ w,
    __half* __restrict__ out, int D)
{
    int row = blockIdx.x;
    const float* xr = x + (size_t)row * D;
    float s = 0.f;
    for (int i = threadIdx.x; i < D; i += 256) { float v = xr[i]; s += v * v; }
    __shared__ float red[8];
    #pragma unroll
    for (int o = 16; o >= 1; o >>= 1) s += __shfl_xor_sync(0xffffffffu, s, o);
    int warp = threadIdx.x >> 5;
    if ((threadIdx.x & 31) == 0) red[warp] = s;
    __syncthreads();
    if (warp == 0) {
        float t = ((threadIdx.x & 31) < 8) ? red[threadIdx.x & 31] : 0.f;
        #pragma unroll
        for (int o = 4; o >= 1; o >>= 1) t += __shfl_xor_sync(0xffffffffu, t, o);
        if (threadIdx.x == 0) red[0] = t;
    }
    __syncthreads();
    float r = rsqrtf(red[0] / (float)D + 1e-6f);
    __half* orow = out + (size_t)row * D;
    for (int i = threadIdx.x; i < D; i += 256)
        orow[i] = __float2half(xr[i] * r * w[i]);
}

// ================= fused: res2 = hidden + kp0 + kp1; xn2 = rmsnorm(res2) (fp16) =====
// One block per row (D = H_DIM = 2048; 256 threads x 8 elements held in registers).
__global__ void __launch_bounds__(256) kred_rmsnorm_kernel(
    const float* __restrict__ kp, const float* __restrict__ hidden,
    const float* __restrict__ w,
    float* __restrict__ res2, __half* __restrict__ xn2)
{
    const int row = blockIdx.x;
    const int D = H_DIM;
    const size_t off = (size_t)row * D;
    const size_t PN = (size_t)L_SEQ * H_DIM;

    float v[8];
    float s = 0.f;
    #pragma unroll
    for (int j = 0; j < 8; j++) {
        int i = threadIdx.x + j * 256;
        float t = hidden[off + i] + kp[off + i] + kp[PN + off + i];
        v[j] = t;
        res2[off + i] = t;
        s += t * t;
    }
    __shared__ float red[8];
    #pragma unroll
    for (int o = 16; o >= 1; o >>= 1) s += __shfl_xor_sync(0xffffffffu, s, o);
    int warp = threadIdx.x >> 5;
    if ((threadIdx.x & 31) == 0) red[warp] = s;
    __syncthreads();
    if (warp == 0) {
        float t = ((threadIdx.x & 31) < 8) ? red[threadIdx.x & 31] : 0.f;
        #pragma unroll
        for (int o = 4; o >= 1; o >>= 1) t += __shfl_xor_sync(0xffffffffu, t, o);
        if (threadIdx.x == 0) red[0] = t;
    }
    __syncthreads();
    float r = rsqrtf(red[0] / (float)D + 1e-6f);
    #pragma unroll
    for (int j = 0; j < 8; j++) {
        int i = threadIdx.x + j * 256;
        xn2[off + i] = __float2half(v[j] * r * w[i]);
    }
}

// ================= HMMA GEMM: C[M,N] = A[M,K] @ B[N,K]^T (both fp16) =================
// 128x128x32 tile, 8 warps (2x4), warp tile 64x32, m16n8k16, cp.async double buffer.
// 2 CTAs/SM. Split-K via gridDim.z (C += z*M*N).   (validated R11 core)
// EPI 0: plain fp32   EPI 1: +bias[n] softplus   EPI 2: +extra[m*N+n]
// EPI 3 (IL=true): interleaved gate/up B rows, stores fp16 silu(g)*u to Ch[m*(N/2)+n/2]
template <int EPI, bool IL>
__global__ void __launch_bounds__(256, 2) hgemm(
    const __half* __restrict__ A, const __half* __restrict__ B,
    float* __restrict__ C, int M, int N, int K,
    const float* __restrict__ extra, __half* __restrict__ Ch)
{
    __shared__ __align__(16) __half As[2][128][40];
    __shared__ __align__(16) __half Bs[2][128][40];

    const int tid = threadIdx.x;
    const int lane = tid & 31;
    const int wid = tid >> 5;
    const int wm = wid >> 2;
    const int wn = wid & 3;
    const int bm = blockIdx.y * 128;
    const int bn = blockIdx.x * 128;
    const int Ksub = K / gridDim.z;
    const int kbase = blockIdx.z * Ksub;
    if (gridDim.z > 1) C += (size_t)blockIdx.z * M * N;

    const uint32_t sA = smem_u32(As);
    const uint32_t sB = smem_u32(Bs);
    const uint32_t ABUF = 128 * 40 * 2;

    float c[4][4][4];
    #pragma unroll
    for (int i = 0; i < 4; i++)
        #pragma unroll
        for (int j = 0; j < 4; j++)
            #pragma unroll
            for (int k = 0; k < 4; k++) c[i][j][k] = 0.f;

    const int lrow = tid >> 2;          // 0..63
    const int lq   = (tid & 3) * 8;
    const int Fh   = N >> 1;

    auto load_tile = [&](int t, int buf) {
        int k0 = kbase + t * 32;
        #pragma unroll
        for (int i = 0; i < 2; i++) {
            int row = lrow + i * 64;
            cp16(sA + buf * ABUF + (row * 40 + lq) * 2,
                 A + (size_t)(bm + row) * K + k0 + lq, 16);
        }
        #pragma unroll
        for (int i = 0; i < 2; i++) {
            int row = lrow + i * 64;
            int gr = bn + row;
            int wr = IL ? ((gr & 1) ? Fh + (gr >> 1) : (gr >> 1)) : gr;
            const __half* src = B + (size_t)(gr < N ? wr : 0) * K + k0 + lq;
            cp16(sB + buf * ABUF + (row * 40 + lq) * 2, src, gr < N ? 16 : 0);
        }
        cp_commit();
    };

    load_tile(0, 0);
    const int nt = Ksub >> 5;

    for (int t = 0; t < nt; t++) {
        cp_wait0();
        __syncthreads();
        if (t + 1 < nt) load_tile(t + 1, (t + 1) & 1);

        const uint32_t aBase = sA + (t & 1) * ABUF;
        const uint32_t bBase = sB + (t & 1) * ABUF;
        #pragma unroll
        for (int ks = 0; ks < 2; ks++) {
            uint32_t a[4][4];
            #pragma unroll
            for (int mf = 0; mf < 4; mf++) {
                int row = wm * 64 + mf * 16 + (lane & 15);
                int col = ks * 16 + (lane >> 4) * 8;
                ldsm4(a[mf][0], a[mf][1], a[mf][2], a[mf][3],
                      aBase + (row * 40 + col) * 2);
            }
            uint32_t b[4][2];
            #pragma unroll
            for (int p = 0; p < 2; p++) {
                int row = wn * 32 + p * 16 + (lane & 7) + ((lane >> 4) << 3);
                int col = ks * 16 + ((lane >> 3) & 1) * 8;
                ldsm4(b[2 * p][0], b[2 * p][1], b[2 * p + 1][0], b[2 * p + 1][1],
                      bBase + (row * 40 + col) * 2);
            }
            #pragma unroll
            for (int mf = 0; mf < 4; mf++)
                #pragma unroll
                for (int nf = 0; nf < 4; nf++)
                    mma16816(c[mf][nf], a[mf], b[nf]);
        }
        __syncthreads();
    }

    // epilogue
    #pragma unroll
    for (int mf = 0; mf < 4; mf++) {
        #pragma unroll
        for (int nf = 0; nf < 4; nf++) {
            int m0 = bm + wm * 64 + mf * 16 + (lane >> 2);
            int n0 = bn + wn * 32 + nf * 8 + (lane & 3) * 2;
            if (n0 < N) {
                #pragma unroll
                for (int hh = 0; hh < 2; hh++) {
                    int m = m0 + hh * 8;
                    float v0 = c[mf][nf][hh * 2 + 0];
                    float v1 = c[mf][nf][hh * 2 + 1];
                    if (EPI == 3) {
                        Ch[(size_t)m * Fh + (n0 >> 1)] = __float2half(silu_f(v0) * v1);
                    } else {
                        if (EPI == 1) {
                            v0 += extra[n0];
                            v1 += extra[n0 + 1];
                            v0 = fmaxf(v0, 0.f) + log1pf(__expf(-fabsf(v0)));
                            v1 = fmaxf(v1, 0.f) + log1pf(__expf(-fabsf(v1)));
                        } else if (EPI == 2) {
                            v0 += extra[(size_t)m * N + n0];
                            v1 += extra[(size_t)m * N + n0 + 1];
                        }
                        *(float2*)(C + (size_t)m * N + n0) = make_float2(v0, v1);
                    }
                }
            }
        }
    }
}

// ================= causal depthwise conv + bias + silu =================
__global__ void __launch_bounds__(256) conv_silu_kernel(
    const float* __restrict__ proj, const float* __restrict__ cw,
    const float* __restrict__ cb, float* __restrict__ h, __half* __restrict__ hh)
{
    int idx = blockIdx.x * 256 + threadIdx.x;
    if (idx >= L_SEQ * DI) return;
    int d = idx & (DI - 1);
    int l = idx >> 12;
    float s = cb[d];
    #pragma unroll
    for (int k = 0; k < KC; k++) {
        int ll = l - (KC - 1) + k;
        if (ll >= 0) s = fmaf(proj[(size_t)ll * (2 * DI) + d], cw[d * KC + k], s);
    }
    float v = silu_f(s);
    h[idx] = v;
    hh[idx] = __float2half(v);
}

// ================= segment rmsnorm + split-K reduce =================
__global__ void __launch_bounds__(32) segnorm_kernel(
    const float* __restrict__ part,
    const float* __restrict__ wdt, const float* __restrict__ wb, const float* __restrict__ wc,
    __half* __restrict__ dtnh, float* __restrict__ Bn, float* __restrict__ Cn)
{
    int l = blockIdx.x;
    int lane = threadIdx.x;
    const float* row = part + (size_t)l * 160;
    const size_t SL = (size_t)L_SEQ * 160;

    float v[4];
    float s = 0.f;
    #pragma unroll
    for (int i = 0; i < 4; i++) {
        float acc = 0.f;
        #pragma unroll
        for (int ks = 0; ks < KSPL; ks++) acc += row[ks * SL + lane * 4 + i];
        v[i] = acc;
        s += acc * acc;
    }
    #pragma unroll
    for (int o = 16; o >= 1; o >>= 1) s += __shfl_xor_sync(0xffffffffu, s, o);
    float r = rsqrtf(s / 128.f + 1e-6f);
    #pragma unroll
    for (int i = 0; i < 4; i++)
        dtnh[(size_t)l * 128 + lane * 4 + i] = __float2half(v[i] * r * wdt[lane * 4 + i]);

    float b = 0.f, c = 0.f;
    if (lane < 16) {
        #pragma unroll
        for (int ks = 0; ks < KSPL; ks++) {
            b += row[ks * SL + 128 + lane];
            c += row[ks * SL + 144 + lane];
        }
    }
    float sb = b * b;
    #pragma unroll
    for (int o = 16; o >= 1; o >>= 1) sb += __shfl_xor_sync(0xffffffffu, sb, o);
    float rb = rsqrtf(sb / 16.f + 1e-6f);
    if (lane < 16) Bn[(size_t)l * 16 + lane] = b * rb * wb[lane];

    float sc = c * c;
    #pragma unroll
    for (int o = 16; o >= 1; o >>= 1) sc += __shfl_xor_sync(0xffffffffu, sc, o);
    float rc = rsqrtf(sc / 16.f + 1e-6f);
    if (lane < 16) Cn[(size_t)l * 16 + lane] = c * rc * wc[lane];
}

// ================= selective scan =================
__global__ void __launch_bounds__(256) scan_kernel(
    const float* __restrict__ delta, const float* __restrict__ Bn,
    const float* __restrict__ Cn, const float* __restrict__ h,
    const float* __restrict__ proj, const float* __restrict__ Am,
    const float* __restrict__ Dv, __half* __restrict__ yh)
{
    int tid = blockIdx.x * 256 + threadIdx.x;
    int d = tid >> 4;
    int n = tid & 15;
    float a = Am[d * NS + n];
    float dval = Dv[d];
    float s = 0.f;
    for (int l = 0; l < L_SEQ; l++) {
        float dl = delta[(size_t)l * DI + d];
        float hl = h[(size_t)l * DI + d];
        float bl = Bn[(size_t)l * NS + n];
        float cl = Cn[(size_t)l * NS + n];
        float dA = __expf(dl * a);
        s = fmaf(dA, s, dl * bl * hl);
        float contrib = s * cl;
        contrib += __shfl_xor_sync(0xffffffffu, contrib, 1);
        contrib += __shfl_xor_sync(0xffffffffu, contrib, 2);
        contrib += __shfl_xor_sync(0xffffffffu, contrib, 4);
        contrib += __shfl_xor_sync(0xffffffffu, contrib, 8);
        if (n == 0) {
            float g = proj[(size_t)l * (2 * DI) + DI + d];
            yh[(size_t)l * DI + d] = __float2half((contrib + hl * dval) * silu_f(g));
        }
    }
}

// ================= launch =================
extern "C" void kernel_launch(void* const* d_in, const int* in_sizes, int n_in,
                              void* d_out, int out_size)
{
    const float* hidden      = (const float*)d_in[0];
    const float* in_ln_w     = (const float*)d_in[1];
    const float* pre_ff_ln_w = (const float*)d_in[2];
    const float* in_proj_w   = (const float*)d_in[3];
    const float* conv_w      = (const float*)d_in[4];
    const float* conv_b      = (const float*)d_in[5];
    const float* x_proj_w    = (const float*)d_in[6];
    const float* dt_ln_w     = (const float*)d_in[7];
    const float* b_ln_w      = (const float*)d_in[8];
    const float* c_ln_w      = (const float*)d_in[9];
    const float* dt_proj_w   = (const float*)d_in[10];
    const float* dt_proj_b   = (const float*)d_in[11];
    const float* A           = (const float*)d_in[12];
    const float* Dv          = (const float*)d_in[13];
    const float* out_proj_w  = (const float*)d_in[14];
    const float* gate_up_w   = (const float*)d_in[15];
    const float* down_w      = (const float*)d_in[16];
    float* out = (float*)d_out;

    float *proj, *h, *part, *kp, *Bn, *Cn, *delta, *res2;
    __half *xnh, *hh, *dtnh, *yh, *xn2h, *acth;
    __half *w_in, *w_x, *w_dt, *w_out, *w_gu, *w_dn;
    cudaGetSymbolAddress((void**)&proj,  g_proj);
    cudaGetSymbolAddress((void**)&h,     g_h);
    cudaGetSymbolAddress((void**)&part,  g_part);
    cudaGetSymbolAddress((void**)&kp,    g_kp);
    cudaGetSymbolAddress((void**)&Bn,    g_Bn);
    cudaGetSymbolAddress((void**)&Cn,    g_Cn);
    cudaGetSymbolAddress((void**)&delta, g_delta);
    cudaGetSymbolAddress((void**)&res2,  g_res2);
    cudaGetSymbolAddress((void**)&xnh,   g_xnh);
    cudaGetSymbolAddress((void**)&hh,    g_hh);
    cudaGetSymbolAddress((void**)&dtnh,  g_dtnh);
    cudaGetSymbolAddress((void**)&yh,    g_yh);
    cudaGetSymbolAddress((void**)&xn2h,  g_xn2h);
    cudaGetSymbolAddress((void**)&acth,  g_acth);
    cudaGetSymbolAddress((void**)&w_in,  g_w_in);
    cudaGetSymbolAddress((void**)&w_x,   g_w_x);
    cudaGetSymbolAddress((void**)&w_dt,  g_w_dt);
    cudaGetSymbolAddress((void**)&w_out, g_w_out);
    cudaGetSymbolAddress((void**)&w_gu,  g_w_gu);
    cudaGetSymbolAddress((void**)&w_dn,  g_w_dn);

    // side stream + events for overlapping weight converts (created once;
    // host-side infra only — identical launched work every call)
    static cudaStream_t s2 = nullptr;
    static cudaEvent_t ev_fork = nullptr, ev_join = nullptr;
    if (s2 == nullptr) {
        cudaStreamCreateWithFlags(&s2, cudaStreamNonBlocking);
        cudaEventCreateWithFlags(&ev_fork, cudaEventDisableTiming);
        cudaEventCreateWithFlags(&ev_join, cudaEventDisableTiming);
    }

    auto cvt = [](cudaStream_t st, const float* s, __half* d, int n) {
        int n4 = n / 4;
        int nthreads = (n4 + 3) / 4;
        f2h_kernel<<<(nthreads + 255) / 256, 256, 0, st>>>(
            (const float4*)s, (uint2*)d, n4);
    };

    const int MH4 = (L_SEQ * H_DIM) / 4;   // float4 count for [1024, 2048]

    // fork: side-stream converts for weights consumed later
    cudaEventRecord(ev_fork, 0);
    cudaStreamWaitEvent(s2, ev_fork, 0);
    cvt(s2, x_proj_w,   w_x,   160 * DI);
    cvt(s2, dt_proj_w,  w_dt,  DI * DT_R);
    cvt(s2, out_proj_w, w_out, H_DIM * DI);
    cvt(s2, gate_up_w,  w_gu,  2 * FF * H_DIM);
    cvt(s2, down_w,     w_dn,  H_DIM * FF);
    cudaEventRecord(ev_join, s2);

    // critical path: only w_in is needed immediately
    cvt(0, in_proj_w, w_in, 2 * DI * H_DIM);

    // 1. xn = rmsnorm(hidden) -> fp16
    rmsnorm_kernel<<<L_SEQ, 256>>>(hidden, in_ln_w, xnh, H_DIM);

    // 2. proj = xn @ in_proj_w^T   [1024, 8192], K=2048  (overlaps with S2 converts)
    hgemm<0, false><<<dim3((2 * DI) / 128, L_SEQ / 128, 1), 256>>>(
        xnh, w_in, proj, L_SEQ, 2 * DI, H_DIM, nullptr, nullptr);

    // 3. h = silu(conv(proj[:, :Di]) + b)
    conv_silu_kernel<<<(L_SEQ * DI) / 256, 256>>>(proj, conv_w, conv_b, h, hh);

    // join: all remaining weights must be converted before their consumers
    cudaStreamWaitEvent(0, ev_join, 0);

    // 4. ssm partials = h @ x_proj_w^T   [1024, 160], K=4096, split-K x8
    hgemm<0, false><<<dim3(2, L_SEQ / 128, KSPL), 256>>>(
        hh, w_x, part, L_SEQ, 160, DI, nullptr, nullptr);

    // 5. segment rmsnorms (+ split-K reduce)
    segnorm_kernel<<<L_SEQ, 32>>>(part, dt_ln_w, b_ln_w, c_ln_w, dtnh, Bn, Cn);

    // 6. delta = softplus(dtn @ dt_proj_w^T + b)   [1024, 4096], K=128
    hgemm<1, false><<<dim3(DI / 128, L_SEQ / 128, 1), 256>>>(
        dtnh, w_dt, delta, L_SEQ, DI, DT_R, dt_proj_b, nullptr);

    // 7. selective scan + skip + gate
    scan_kernel<<<(DI * NS) / 256, 256>>>(delta, Bn, Cn, h, proj, A, Dv, yh);

    // 8. out_proj split-K x2 -> partials
    hgemm<0, false><<<dim3(H_DIM / 128, L_SEQ / 128, 2), 256>>>(
        yh, w_out, kp, L_SEQ, H_DIM, DI, nullptr, nullptr);

    // 9. fused: res2 = hidden + kp0 + kp1; xn2 = rmsnorm(res2) -> fp16
    kred_rmsnorm_kernel<<<L_SEQ, 256>>>(kp, hidden, pre_ff_ln_w, res2, xn2h);

    // 10+11. act = silu(gate)*up fused into gate_up GEMM (interleaved columns)
    hgemm<3, true><<<dim3((2 * FF) / 128, L_SEQ / 128, 1), 256>>>(
        xn2h, w_gu, nullptr, L_SEQ, 2 * FF, H_DIM, nullptr, acth);

    // 12. down split-K x2 -> partials; out = res2 + kp0 + kp1
    hgemm<0, false><<<dim3(H_DIM / 128, L_SEQ / 128, 2), 256>>>(
        acth, w_dn, kp, L_SEQ, H_DIM, FF, nullptr, nullptr);
    kred_kernel<<<(MH4 + 255) / 256, 256>>>(
        (const float4*)kp, (const float4*)res2, (float4*)out, MH4);
}

// round 14
// speedup vs baseline: 1.7355x; 1.7072x over previous
#include <cuda_runtime.h>
#include <cuda_fp16.h>
#include <math.h>
#include <stdint.h>

#define L_SEQ 1024
#define H_DIM 2048
#define DI    4096
#define DT_R  128
#define NS    16
#define KC    4
#define FF    8192
#define KSPL  8

// ---------------- scratch ----------------
__device__ float g_proj [L_SEQ * 2 * DI];
__device__ float g_h    [L_SEQ * DI];
__device__ float g_part [KSPL * L_SEQ * 160];
__device__ float g_kp   [2 * L_SEQ * H_DIM];    // split-K partials for out/down GEMMs
__device__ float g_Bn   [L_SEQ * NS];
__device__ float g_Cn   [L_SEQ * NS];
__device__ float g_delta[L_SEQ * DI];
__device__ float g_res2 [L_SEQ * H_DIM];
// fp16 activations
__device__ __half g_xnh  [L_SEQ * H_DIM];
__device__ __half g_hh   [L_SEQ * DI];
__device__ __half g_dtnh [L_SEQ * DT_R];
__device__ __half g_yh   [L_SEQ * DI];
__device__ __half g_xn2h [L_SEQ * H_DIM];
__device__ __half g_acth [L_SEQ * FF];
// fp16 weights
__device__ __half g_w_in [2 * DI * H_DIM];
__device__ __half g_w_x  [160 * DI];
__device__ __half g_w_dt [DI * DT_R];
__device__ __half g_w_out[H_DIM * DI];
__device__ __half g_w_gu [2 * FF * H_DIM];
__device__ __half g_w_dn [H_DIM * FF];

// ================= PTX helpers =================
__device__ __forceinline__ uint32_t smem_u32(const void* p) {
    uint32_t a;
    asm("{ .reg .u64 t; cvta.to.shared.u64 t, %1; cvt.u32.u64 %0, t; }" : "=r"(a) : "l"(p));
    return a;
}
__device__ __forceinline__ void cp16(uint32_t dst, const void* src, int sz) {
    asm volatile("cp.async.cg.shared.global [%0], [%1], 16, %2;"
                 :: "r"(dst), "l"(src), "r"(sz));
}
__device__ __forceinline__ void cp_commit() {
    asm volatile("cp.async.commit_group;" ::: "memory");
}
__device__ __forceinline__ void cp_wait0() {
    asm volatile("cp.async.wait_group 0;" ::: "memory");
}
__device__ __forceinline__ void ldsm4(uint32_t& r0, uint32_t& r1, uint32_t& r2, uint32_t& r3, uint32_t a) {
    asm volatile("ldmatrix.sync.aligned.m8n8.x4.shared.b16 {%0,%1,%2,%3}, [%4];"
                 : "=r"(r0), "=r"(r1), "=r"(r2), "=r"(r3) : "r"(a));
}
__device__ __forceinline__ void mma16816(float* c, const uint32_t* a, const uint32_t* b) {
    asm volatile("mma.sync.aligned.m16n8k16.row.col.f32.f16.f16.f32 "
                 "{%0,%1,%2,%3}, {%4,%5,%6,%7}, {%8,%9}, {%0,%1,%2,%3};"
                 : "+f"(c[0]), "+f"(c[1]), "+f"(c[2]), "+f"(c[3])
                 : "r"(a[0]), "r"(a[1]), "r"(a[2]), "r"(a[3]), "r"(b[0]), "r"(b[1]));
}

__device__ __forceinline__ float silu_f(float x) { return x / (1.f + __expf(-x)); }

// ================= fp32 -> fp16 convert (4 float4 per thread) =================
__global__ void __launch_bounds__(256) f2h_kernel(const float4* __restrict__ s,
                                                  uint2* __restrict__ d, int n4) {
    int base = (blockIdx.x * 256 + threadIdx.x) * 4;
    if (base + 3 >= n4) {
        for (int j = 0; j < 4; j++) {
            int i = base + j;
            if (i < n4) {
                float4 v = s[i];
                __half2 a = __floats2half2_rn(v.x, v.y);
                __half2 b = __floats2half2_rn(v.z, v.w);
                uint2 o;
                o.x = *reinterpret_cast<uint32_t*>(&a);
                o.y = *reinterpret_cast<uint32_t*>(&b);
                d[i] = o;
            }
        }
        return;
    }
    float4 v0 = s[base + 0];
    float4 v1 = s[base + 1];
    float4 v2 = s[base + 2];
    float4 v3 = s[base + 3];
    #pragma unroll
    for (int j = 0; j < 4; j++) {
        float4 v = (j == 0) ? v0 : (j == 1) ? v1 : (j == 2) ? v2 : v3;
        __half2 a = __floats2half2_rn(v.x, v.y);
        __half2 b = __floats2half2_rn(v.z, v.w);
        uint2 o;
        o.x = *reinterpret_cast<uint32_t*>(&a);
        o.y = *reinterpret_cast<uint32_t*>(&b);
        d[base + j] = o;
    }
}

// ================= split-K reduce + residual: dst = res + p0 + p1 =================
__global__ void __launch_bounds__(256) kred_kernel(
    const float4* __restrict__ p, const float4* __restrict__ res,
    float4* __restrict__ dst, int n4)
{
    int i = blockIdx.x * 256 + threadIdx.x;
    if (i >= n4) return;
    float4 a = p[i];
    float4 b = p[i + n4];
    float4 r = res[i];
    dst[i] = make_float4(r.x + a.x + b.x, r.y + a.y + b.y,
                         r.z + a.z + b.z, r.w + a.w + b.w);
}

// ================= rmsnorm (fp32 in, fp16 out) =================
__global__ void __launch_bounds__(256) rmsnorm_kernel(
    const float* __restrict__ x, const float* __restrict__ w,
    __half* __restrict__ out, int D)
{
    int row = blockIdx.x;
    const float* xr = x + (size_t)row * D;
    float s = 0.f;
    for (int i = threadIdx.x; i < D; i += 256) { float v = xr[i]; s += v * v; }
    __shared__ float red[8];
    #pragma unroll
    for (int o = 16; o >= 1; o >>= 1) s += __shfl_xor_sync(0xffffffffu, s, o);
    int warp = threadIdx.x >> 5;
    if ((threadIdx.x & 31) == 0) red[warp] = s;
    __syncthreads();
    if (warp == 0) {
        float t = ((threadIdx.x & 31) < 8) ? red[threadIdx.x & 31] : 0.f;
        #pragma unroll
        for (int o = 4; o >= 1; o >>= 1) t += __shfl_xor_sync(0xffffffffu, t, o);
        if (threadIdx.x == 0) red[0] = t;
    }
    __syncthreads();
    float r = rsqrtf(red[0] / (float)D + 1e-6f);
    __half* orow = out + (size_t)row * D;
    for (int i = threadIdx.x; i < D; i += 256)
        orow[i] = __float2half(xr[i] * r * w[i]);
}

// ================= fused: res2 = hidden + kp0 + kp1; xn2 = rmsnorm(res2) (fp16) =====
__global__ void __launch_bounds__(256) kred_rmsnorm_kernel(
    const float* __restrict__ kp, const float* __restrict__ hidden,
    const float* __restrict__ w,
    float* __restrict__ res2, __half* __restrict__ xn2)
{
    const int row = blockIdx.x;
    const int D = H_DIM;
    const size_t off = (size_t)row * D;
    const size_t PN = (size_t)L_SEQ * H_DIM;

    float v[8];
    float s = 0.f;
    #pragma unroll
    for (int j = 0; j < 8; j++) {
        int i = threadIdx.x + j * 256;
        float t = hidden[off + i] + kp[off + i] + kp[PN + off + i];
        v[j] = t;
        res2[off + i] = t;
        s += t * t;
    }
    __shared__ float red[8];
    #pragma unroll
    for (int o = 16; o >= 1; o >>= 1) s += __shfl_xor_sync(0xffffffffu, s, o);
    int warp = threadIdx.x >> 5;
    if ((threadIdx.x & 31) == 0) red[warp] = s;
    __syncthreads();
    if (warp == 0) {
        float t = ((threadIdx.x & 31) < 8) ? red[threadIdx.x & 31] : 0.f;
        #pragma unroll
        for (int o = 4; o >= 1; o >>= 1) t += __shfl_xor_sync(0xffffffffu, t, o);
        if (threadIdx.x == 0) red[0] = t;
    }
    __syncthreads();
    float r = rsqrtf(red[0] / (float)D + 1e-6f);
    #pragma unroll
    for (int j = 0; j < 8; j++) {
        int i = threadIdx.x + j * 256;
        xn2[off + i] = __float2half(v[j] * r * w[i]);
    }
}

// ================= HMMA GEMM: C[M,N] = A[M,K] @ B[N,K]^T (both fp16) =================
// 128x128x32 tile, 8 warps (2x4), warp tile 64x32, m16n8k16, cp.async double buffer.
// 2 CTAs/SM. Split-K via gridDim.z (C += z*M*N).   (validated R11 core)
// EPI 0: plain fp32   EPI 1: +bias[n] softplus   EPI 2: +extra[m*N+n]
// EPI 3 (IL=true): interleaved gate/up B rows, stores fp16 silu(g)*u to Ch[m*(N/2)+n/2]
template <int EPI, bool IL>
__global__ void __launch_bounds__(256, 2) hgemm(
    const __half* __restrict__ A, const __half* __restrict__ B,
    float* __restrict__ C, int M, int N, int K,
    const float* __restrict__ extra, __half* __restrict__ Ch)
{
    __shared__ __align__(16) __half As[2][128][40];
    __shared__ __align__(16) __half Bs[2][128][40];

    const int tid = threadIdx.x;
    const int lane = tid & 31;
    const int wid = tid >> 5;
    const int wm = wid >> 2;
    const int wn = wid & 3;
    const int bm = blockIdx.y * 128;
    const int bn = blockIdx.x * 128;
    const int Ksub = K / gridDim.z;
    const int kbase = blockIdx.z * Ksub;
    if (gridDim.z > 1) C += (size_t)blockIdx.z * M * N;

    const uint32_t sA = smem_u32(As);
    const uint32_t sB = smem_u32(Bs);
    const uint32_t ABUF = 128 * 40 * 2;

    float c[4][4][4];
    #pragma unroll
    for (int i = 0; i < 4; i++)
        #pragma unroll
        for (int j = 0; j < 4; j++)
            #pragma unroll
            for (int k = 0; k < 4; k++) c[i][j][k] = 0.f;

    const int lrow = tid >> 2;          // 0..63
    const int lq   = (tid & 3) * 8;
    const int Fh   = N >> 1;

    auto load_tile = [&](int t, int buf) {
        int k0 = kbase + t * 32;
        #pragma unroll
        for (int i = 0; i < 2; i++) {
            int row = lrow + i * 64;
            cp16(sA + buf * ABUF + (row * 40 + lq) * 2,
                 A + (size_t)(bm + row) * K + k0 + lq, 16);
        }
        #pragma unroll
        for (int i = 0; i < 2; i++) {
            int row = lrow + i * 64;
            int gr = bn + row;
            int wr = IL ? ((gr & 1) ? Fh + (gr >> 1) : (gr >> 1)) : gr;
            const __half* src = B + (size_t)(gr < N ? wr : 0) * K + k0 + lq;
            cp16(sB + buf * ABUF + (row * 40 + lq) * 2, src, gr < N ? 16 : 0);
        }
        cp_commit();
    };

    load_tile(0, 0);
    const int nt = Ksub >> 5;

    for (int t = 0; t < nt; t++) {
        cp_wait0();
        __syncthreads();
        if (t + 1 < nt) load_tile(t + 1, (t + 1) & 1);

        const uint32_t aBase = sA + (t & 1) * ABUF;
        const uint32_t bBase = sB + (t & 1) * ABUF;
        #pragma unroll
        for (int ks = 0; ks < 2; ks++) {
            uint32_t a[4][4];
            #pragma unroll
            for (int mf = 0; mf < 4; mf++) {
                int row = wm * 64 + mf * 16 + (lane & 15);
                int col = ks * 16 + (lane >> 4) * 8;
                ldsm4(a[mf][0], a[mf][1], a[mf][2], a[mf][3],
                      aBase + (row * 40 + col) * 2);
            }
            uint32_t b[4][2];
            #pragma unroll
            for (int p = 0; p < 2; p++) {
                int row = wn * 32 + p * 16 + (lane & 7) + ((lane >> 4) << 3);
                int col = ks * 16 + ((lane >> 3) & 1) * 8;
                ldsm4(b[2 * p][0], b[2 * p][1], b[2 * p + 1][0], b[2 * p + 1][1],
                      bBase + (row * 40 + col) * 2);
            }
            #pragma unroll
            for (int mf = 0; mf < 4; mf++)
                #pragma unroll
                for (int nf = 0; nf < 4; nf++)
                    mma16816(c[mf][nf], a[mf], b[nf]);
        }
        __syncthreads();
    }

    // epilogue
    #pragma unroll
    for (int mf = 0; mf < 4; mf++) {
        #pragma unroll
        for (int nf = 0; nf < 4; nf++) {
            int m0 = bm + wm * 64 + mf * 16 + (lane >> 2);
            int n0 = bn + wn * 32 + nf * 8 + (lane & 3) * 2;
            if (n0 < N) {
                #pragma unroll
                for (int hh = 0; hh < 2; hh++) {
                    int m = m0 + hh * 8;
                    float v0 = c[mf][nf][hh * 2 + 0];
                    float v1 = c[mf][nf][hh * 2 + 1];
                    if (EPI == 3) {
                        Ch[(size_t)m * Fh + (n0 >> 1)] = __float2half(silu_f(v0) * v1);
                    } else {
                        if (EPI == 1) {
                            v0 += extra[n0];
                            v1 += extra[n0 + 1];
                            v0 = fmaxf(v0, 0.f) + log1pf(__expf(-fabsf(v0)));
                            v1 = fmaxf(v1, 0.f) + log1pf(__expf(-fabsf(v1)));
                        } else if (EPI == 2) {
                            v0 += extra[(size_t)m * N + n0];
                            v1 += extra[(size_t)m * N + n0 + 1];
                        }
                        *(float2*)(C + (size_t)m * N + n0) = make_float2(v0, v1);
                    }
                }
            }
        }
    }
}

// ================= causal depthwise conv + bias + silu =================
__global__ void __launch_bounds__(256) conv_silu_kernel(
    const float* __restrict__ proj, const float* __restrict__ cw,
    const float* __restrict__ cb, float* __restrict__ h, __half* __restrict__ hh)
{
    int idx = blockIdx.x * 256 + threadIdx.x;
    if (idx >= L_SEQ * DI) return;
    int d = idx & (DI - 1);
    int l = idx >> 12;
    float s = cb[d];
    #pragma unroll
    for (int k = 0; k < KC; k++) {
        int ll = l - (KC - 1) + k;
        if (ll >= 0) s = fmaf(proj[(size_t)ll * (2 * DI) + d], cw[d * KC + k], s);
    }
    float v = silu_f(s);
    h[idx] = v;
    hh[idx] = __float2half(v);
}

// ================= segment rmsnorm + split-K reduce =================
__global__ void __launch_bounds__(32) segnorm_kernel(
    const float* __restrict__ part,
    const float* __restrict__ wdt, const float* __restrict__ wb, const float* __restrict__ wc,
    __half* __restrict__ dtnh, float* __restrict__ Bn, float* __restrict__ Cn)
{
    int l = blockIdx.x;
    int lane = threadIdx.x;
    const float* row = part + (size_t)l * 160;
    const size_t SL = (size_t)L_SEQ * 160;

    float v[4];
    float s = 0.f;
    #pragma unroll
    for (int i = 0; i < 4; i++) {
        float acc = 0.f;
        #pragma unroll
        for (int ks = 0; ks < KSPL; ks++) acc += row[ks * SL + lane * 4 + i];
        v[i] = acc;
        s += acc * acc;
    }
    #pragma unroll
    for (int o = 16; o >= 1; o >>= 1) s += __shfl_xor_sync(0xffffffffu, s, o);
    float r = rsqrtf(s / 128.f + 1e-6f);
    #pragma unroll
    for (int i = 0; i < 4; i++)
        dtnh[(size_t)l * 128 + lane * 4 + i] = __float2half(v[i] * r * wdt[lane * 4 + i]);

    float b = 0.f, c = 0.f;
    if (lane < 16) {
        #pragma unroll
        for (int ks = 0; ks < KSPL; ks++) {
            b += row[ks * SL + 128 + lane];
            c += row[ks * SL + 144 + lane];
        }
    }
    float sb = b * b;
    #pragma unroll
    for (int o = 16; o >= 1; o >>= 1) sb += __shfl_xor_sync(0xffffffffu, sb, o);
    float rb = rsqrtf(sb / 16.f + 1e-6f);
    if (lane < 16) Bn[(size_t)l * 16 + lane] = b * rb * wb[lane];

    float sc = c * c;
    #pragma unroll
    for (int o = 16; o >= 1; o >>= 1) sc += __shfl_xor_sync(0xffffffffu, sc, o);
    float rc = rsqrtf(sc / 16.f + 1e-6f);
    if (lane < 16) Cn[(size_t)l * 16 + lane] = c * rc * wc[lane];
}

// ================= selective scan (smem-staged, coalesced) =================
// Block = 256 threads = 16 d-channels x 16 states. Each block owns d-range
// [blockIdx.x*16, +16) and loops over L in chunks of 64, staging all operand
// tiles in smem with coalesced loads. Math identical to the naive version.
#define SCH 64
__global__ void __launch_bounds__(256) scan_kernel(
    const float* __restrict__ delta, const float* __restrict__ Bn,
    const float* __restrict__ Cn, const float* __restrict__ h,
    const float* __restrict__ proj, const float* __restrict__ Am,
    const float* __restrict__ Dv, __half* __restrict__ yh)
{
    __shared__ float sD[SCH][16];
    __shared__ float sH[SCH][16];
    __shared__ float sG[SCH][16];
    __shared__ float sB[SCH][16];
    __shared__ float sC[SCH][16];
    __shared__ __half sY[SCH][16];

    const int tid = threadIdx.x;
    const int dg = tid >> 4;        // local channel 0..15
    const int n  = tid & 15;        // state index
    const int d0 = blockIdx.x * 16;
    const int d  = d0 + dg;

    const float a    = Am[d * NS + n];
    const float dval = Dv[d];
    float s = 0.f;

    const int lr = tid >> 4;        // staging row (16 rows per pass)
    const int lc = tid & 15;        // staging col

    for (int l0 = 0; l0 < L_SEQ; l0 += SCH) {
        __syncthreads();            // previous chunk's sY flush complete
        #pragma unroll
        for (int r = lr; r < SCH; r += 16) {
            int l = l0 + r;
            sD[r][lc] = delta[(size_t)l * DI + d0 + lc];
            sH[r][lc] = h[(size_t)l * DI + d0 + lc];
            sG[r][lc] = proj[(size_t)l * (2 * DI) + DI + d0 + lc];
            sB[r][lc] = Bn[(size_t)l * 16 + lc];
            sC[r][lc] = Cn[(size_t)l * 16 + lc];
        }
        __syncthreads();

        for (int r = 0; r < SCH; r++) {
            float dl = sD[r][dg];
            float hl = sH[r][dg];
            float bl = sB[r][n];
            float cl = sC[r][n];
            float dA = __expf(dl * a);
            s = fmaf(dA, s, dl * bl * hl);
            float contrib = s * cl;
            contrib += __shfl_xor_sync(0xffffffffu, contrib, 1);
            contrib += __shfl_xor_sync(0xffffffffu, contrib, 2);
            contrib += __shfl_xor_sync(0xffffffffu, contrib, 4);
            contrib += __shfl_xor_sync(0xffffffffu, contrib, 8);
            if (n == 0)
                sY[r][dg] = __float2half((contrib + hl * dval) * silu_f(sG[r][dg]));
        }
        __syncthreads();
        #pragma unroll
        for (int r = lr; r < SCH; r += 16)
            yh[(size_t)(l0 + r) * DI + d0 + lc] = sY[r][lc];
    }
}

// ================= launch =================
extern "C" void kernel_launch(void* const* d_in, const int* in_sizes, int n_in,
                              void* d_out, int out_size)
{
    const float* hidden      = (const float*)d_in[0];
    const float* in_ln_w     = (const float*)d_in[1];
    const float* pre_ff_ln_w = (const float*)d_in[2];
    const float* in_proj_w   = (const float*)d_in[3];
    const float* conv_w      = (const float*)d_in[4];
    const float* conv_b      = (const float*)d_in[5];
    const float* x_proj_w    = (const float*)d_in[6];
    const float* dt_ln_w     = (const float*)d_in[7];
    const float* b_ln_w      = (const float*)d_in[8];
    const float* c_ln_w      = (const float*)d_in[9];
    const float* dt_proj_w   = (const float*)d_in[10];
    const float* dt_proj_b   = (const float*)d_in[11];
    const float* A           = (const float*)d_in[12];
    const float* Dv          = (const float*)d_in[13];
    const float* out_proj_w  = (const float*)d_in[14];
    const float* gate_up_w   = (const float*)d_in[15];
    const float* down_w      = (const float*)d_in[16];
    float* out = (float*)d_out;

    float *proj, *h, *part, *kp, *Bn, *Cn, *delta, *res2;
    __half *xnh, *hh, *dtnh, *yh, *xn2h, *acth;
    __half *w_in, *w_x, *w_dt, *w_out, *w_gu, *w_dn;
    cudaGetSymbolAddress((void**)&proj,  g_proj);
    cudaGetSymbolAddress((void**)&h,     g_h);
    cudaGetSymbolAddress((void**)&part,  g_part);
    cudaGetSymbolAddress((void**)&kp,    g_kp);
    cudaGetSymbolAddress((void**)&Bn,    g_Bn);
    cudaGetSymbolAddress((void**)&Cn,    g_Cn);
    cudaGetSymbolAddress((void**)&delta, g_delta);
    cudaGetSymbolAddress((void**)&res2,  g_res2);
    cudaGetSymbolAddress((void**)&xnh,   g_xnh);
    cudaGetSymbolAddress((void**)&hh,    g_hh);
    cudaGetSymbolAddress((void**)&dtnh,  g_dtnh);
    cudaGetSymbolAddress((void**)&yh,    g_yh);
    cudaGetSymbolAddress((void**)&xn2h,  g_xn2h);
    cudaGetSymbolAddress((void**)&acth,  g_acth);
    cudaGetSymbolAddress((void**)&w_in,  g_w_in);
    cudaGetSymbolAddress((void**)&w_x,   g_w_x);
    cudaGetSymbolAddress((void**)&w_dt,  g_w_dt);
    cudaGetSymbolAddress((void**)&w_out, g_w_out);
    cudaGetSymbolAddress((void**)&w_gu,  g_w_gu);
    cudaGetSymbolAddress((void**)&w_dn,  g_w_dn);

    // side stream + events for overlapping weight converts (created once;
    // host-side infra only — identical launched work every call)
    static cudaStream_t s2 = nullptr;
    static cudaEvent_t ev_fork = nullptr, ev_join = nullptr;
    if (s2 == nullptr) {
        cudaStreamCreateWithFlags(&s2, cudaStreamNonBlocking);
        cudaEventCreateWithFlags(&ev_fork, cudaEventDisableTiming);
        cudaEventCreateWithFlags(&ev_join, cudaEventDisableTiming);
    }

    auto cvt = [](cudaStream_t st, const float* s, __half* d, int n) {
        int n4 = n / 4;
        int nthreads = (n4 + 3) / 4;
        f2h_kernel<<<(nthreads + 255) / 256, 256, 0, st>>>(
            (const float4*)s, (uint2*)d, n4);
    };

    const int MH4 = (L_SEQ * H_DIM) / 4;   // float4 count for [1024, 2048]

    // fork: side-stream converts for weights consumed later
    cudaEventRecord(ev_fork, 0);
    cudaStreamWaitEvent(s2, ev_fork, 0);
    cvt(s2, x_proj_w,   w_x,   160 * DI);
    cvt(s2, dt_proj_w,  w_dt,  DI * DT_R);
    cvt(s2, out_proj_w, w_out, H_DIM * DI);
    cvt(s2, gate_up_w,  w_gu,  2 * FF * H_DIM);
    cvt(s2, down_w,     w_dn,  H_DIM * FF);
    cudaEventRecord(ev_join, s2);

    // critical path: only w_in is needed immediately
    cvt(0, in_proj_w, w_in, 2 * DI * H_DIM);

    // 1. xn = rmsnorm(hidden) -> fp16
    rmsnorm_kernel<<<L_SEQ, 256>>>(hidden, in_ln_w, xnh, H_DIM);

    // 2. proj = xn @ in_proj_w^T   [1024, 8192], K=2048  (overlaps with S2 converts)
    hgemm<0, false><<<dim3((2 * DI) / 128, L_SEQ / 128, 1), 256>>>(
        xnh, w_in, proj, L_SEQ, 2 * DI, H_DIM, nullptr, nullptr);

    // 3. h = silu(conv(proj[:, :Di]) + b)
    conv_silu_kernel<<<(L_SEQ * DI) / 256, 256>>>(proj, conv_w, conv_b, h, hh);

    // join: all remaining weights must be converted before their consumers
    cudaStreamWaitEvent(0, ev_join, 0);

    // 4. ssm partials = h @ x_proj_w^T   [1024, 160], K=4096, split-K x8
    hgemm<0, false><<<dim3(2, L_SEQ / 128, KSPL), 256>>>(
        hh, w_x, part, L_SEQ, 160, DI, nullptr, nullptr);

    // 5. segment rmsnorms (+ split-K reduce)
    segnorm_kernel<<<L_SEQ, 32>>>(part, dt_ln_w, b_ln_w, c_ln_w, dtnh, Bn, Cn);

    // 6. delta = softplus(dtn @ dt_proj_w^T + b)   [1024, 4096], K=128
    hgemm<1, false><<<dim3(DI / 128, L_SEQ / 128, 1), 256>>>(
        dtnh, w_dt, delta, L_SEQ, DI, DT_R, dt_proj_b, nullptr);

    // 7. selective scan + skip + gate (smem-staged)
    scan_kernel<<<DI / 16, 256>>>(delta, Bn, Cn, h, proj, A, Dv, yh);

    // 8. out_proj split-K x2 -> partials
    hgemm<0, false><<<dim3(H_DIM / 128, L_SEQ / 128, 2), 256>>>(
        yh, w_out, kp, L_SEQ, H_DIM, DI, nullptr, nullptr);

    // 9. fused: res2 = hidden + kp0 + kp1; xn2 = rmsnorm(res2) -> fp16
    kred_rmsnorm_kernel<<<L_SEQ, 256>>>(kp, hidden, pre_ff_ln_w, res2, xn2h);

    // 10+11. act = silu(gate)*up fused into gate_up GEMM (interleaved columns)
    hgemm<3, true><<<dim3((2 * FF) / 128, L_SEQ / 128, 1), 256>>>(
        xn2h, w_gu, nullptr, L_SEQ, 2 * FF, H_DIM, nullptr, acth);

    // 12. down split-K x2 -> partials; out = res2 + kp0 + kp1
    hgemm<0, false><<<dim3(H_DIM / 128, L_SEQ / 128, 2), 256>>>(
        acth, w_dn, kp, L_SEQ, H_DIM, FF, nullptr, nullptr);
    kred_kernel<<<(MH4 + 255) / 256, 256>>>(
        (const float4*)kp, (const float4*)res2, (float4*)out, MH4);
}